// round 15
// baseline (speedup 1.0000x reference)
#include <cuda_runtime.h>
#include <math.h>

#define BATCH 64
#define NBINS 256
#define TPB 256
#define ELEMS_PER_BLOCK 32768   // 786432 / 32768 = 24 blocks per batch
#define NREP 8                  // per-warp smem hist replicas

// All state zero-initialized at module load; every launch leaves it zeroed
// again (resets folded into entropy_kernel), so no init kernel is needed.
__device__ unsigned int g_minenc[BATCH];   // max of ~ford(x)  (identity 0)
__device__ unsigned int g_maxenc[BATCH];   // max of  ford(x)  (identity 0)
__device__ unsigned int g_hist[BATCH * NBINS];
__device__ float        g_entsum;
__device__ unsigned int g_count;

// monotonic float -> uint mapping (order-preserving)
__device__ __forceinline__ unsigned int ford(float f) {
    unsigned int u = __float_as_uint(f);
    return (u & 0x80000000u) ? ~u : (u | 0x80000000u);
}
__device__ __forceinline__ float funord(unsigned int u) {
    u = (u & 0x80000000u) ? (u ^ 0x80000000u) : ~u;
    return __uint_as_float(u);
}

__global__ void minmax_kernel(const float4* __restrict__ x) {
    const int b = blockIdx.y;
    const int nper4 = gridDim.x * (ELEMS_PER_BLOCK / 4);
    long base = (long)b * nper4 + (long)blockIdx.x * (ELEMS_PER_BLOCK / 4);

    float lmin = INFINITY, lmax = -INFINITY;
    #pragma unroll 8
    for (int i = 0; i < ELEMS_PER_BLOCK / 4 / TPB; i++) {
        float4 v = x[base + (long)i * TPB + threadIdx.x];
        lmin = fminf(fminf(fminf(lmin, v.x), v.y), fminf(v.z, v.w));
        lmax = fmaxf(fmaxf(fmaxf(lmax, v.x), v.y), fmaxf(v.z, v.w));
    }
    #pragma unroll
    for (int o = 16; o; o >>= 1) {
        lmin = fminf(lmin, __shfl_xor_sync(0xFFFFFFFFu, lmin, o));
        lmax = fmaxf(lmax, __shfl_xor_sync(0xFFFFFFFFu, lmax, o));
    }
    __shared__ float smin[TPB / 32], smax[TPB / 32];
    int w = threadIdx.x >> 5;
    if ((threadIdx.x & 31) == 0) { smin[w] = lmin; smax[w] = lmax; }
    __syncthreads();
    if (threadIdx.x == 0) {
        float m = smin[0], M = smax[0];
        #pragma unroll
        for (int i = 1; i < TPB / 32; i++) { m = fminf(m, smin[i]); M = fmaxf(M, smax[i]); }
        atomicMax(&g_minenc[b], ~ford(m));   // min via complement -> max, identity 0
        atomicMax(&g_maxenc[b], ford(M));
    }
}

__global__ void hist_kernel(const float4* __restrict__ x) {
    __shared__ unsigned int sh[NREP * NBINS];
    const int b = blockIdx.y;
    const int nper4 = gridDim.x * (ELEMS_PER_BLOCK / 4);

    for (int i = threadIdx.x; i < NREP * NBINS; i += TPB) sh[i] = 0u;
    __syncthreads();

    const float mn = funord(~g_minenc[b]);
    const float mx = funord(g_maxenc[b]);
    // torch.histc degenerate handling: min==max -> [min-1, max+1], rng=2
    const float rng = (mx > mn) ? (mx - mn) : 2.0f;
    const float lo  = (mx > mn) ? mn : (mn - 1.0f);
    const float scale = (float)NBINS / rng;   // matches jnp: NBINS / rng in f32

    unsigned int* myh = sh + ((threadIdx.x >> 5) & (NREP - 1)) * NBINS;
    long base = (long)b * nper4 + (long)blockIdx.x * (ELEMS_PER_BLOCK / 4);

    #pragma unroll 8
    for (int i = 0; i < ELEMS_PER_BLOCK / 4 / TPB; i++) {
        float4 v = x[base + (long)i * TPB + threadIdx.x];
        int i0 = min(max((int)((v.x - lo) * scale), 0), NBINS - 1);
        int i1 = min(max((int)((v.y - lo) * scale), 0), NBINS - 1);
        int i2 = min(max((int)((v.z - lo) * scale), 0), NBINS - 1);
        int i3 = min(max((int)((v.w - lo) * scale), 0), NBINS - 1);
        atomicAdd(&myh[i0], 1u);
        atomicAdd(&myh[i1], 1u);
        atomicAdd(&myh[i2], 1u);
        atomicAdd(&myh[i3], 1u);
    }
    __syncthreads();

    for (int bin = threadIdx.x; bin < NBINS; bin += TPB) {
        unsigned int s = 0;
        #pragma unroll
        for (int r = 0; r < NREP; r++) s += sh[r * NBINS + bin];
        if (s) atomicAdd(&g_hist[b * NBINS + bin], s);
    }
}

// H(b) = log2(N) - (1/N) * sum_h h*log2(h); last block writes mean and resets
// ALL device state to zero so the next graph replay starts clean.
__global__ void entropy_kernel(float* out, float invN, float log2N) {
    const int b = blockIdx.x;
    unsigned int h = g_hist[b * NBINS + threadIdx.x];
    g_hist[b * NBINS + threadIdx.x] = 0u;             // reset for next replay
    float term = (h > 0u) ? (float)h * log2f((float)h) : 0.0f;
    #pragma unroll
    for (int o = 16; o; o >>= 1) term += __shfl_xor_sync(0xFFFFFFFFu, term, o);
    __shared__ float s[TPB / 32];
    if ((threadIdx.x & 31) == 0) s[threadIdx.x >> 5] = term;
    __syncthreads();
    if (threadIdx.x == 0) {
        float sum = 0.0f;
        #pragma unroll
        for (int i = 0; i < TPB / 32; i++) sum += s[i];
        float ent = log2N - sum * invN;
        atomicAdd(&g_entsum, ent);
        g_minenc[b] = 0u;                             // reset min/max state
        g_maxenc[b] = 0u;
        __threadfence();
        unsigned int old = atomicAdd(&g_count, 1u);
        if (old == BATCH - 1) {
            float total = atomicAdd(&g_entsum, 0.0f); // coherent read of final sum
            out[0] = total * (1.0f / BATCH);
            g_entsum = 0.0f;                          // reset accumulators
            g_count = 0u;
        }
    }
}

extern "C" void kernel_launch(void* const* d_in, const int* in_sizes, int n_in,
                              void* d_out, int out_size) {
    const float4* x = (const float4*)d_in[0];
    float* out = (float*)d_out;

    const int n = in_sizes[0];                          // 64*3*512*512
    const int nper = n / BATCH;                         // 786432
    const int blocksPerBatch = nper / ELEMS_PER_BLOCK;  // 24

    dim3 grid(blocksPerBatch, BATCH);
    minmax_kernel<<<grid, TPB>>>(x);
    hist_kernel<<<grid, TPB>>>(x);

    float invN = 1.0f / (float)nper;
    float log2N = log2f((float)nper);
    entropy_kernel<<<BATCH, TPB>>>(out, invN, log2N);
}

// round 16
// speedup vs baseline: 1.0214x; 1.0214x over previous
#include <cuda_runtime.h>
#include <math.h>

#define BATCH 64
#define NBINS 256
#define TPB 256
#define ELEMS_PER_BLOCK 32768   // 786432 / 32768 = 24 blocks per batch
#define NREP 8                  // per-warp smem hist replicas

// All state zero-initialized at module load; every launch leaves it zeroed
// again (resets folded into entropy_kernel), so no init kernel is needed.
__device__ unsigned int g_minenc[BATCH];   // max of ~ford(x)  (identity 0)
__device__ unsigned int g_maxenc[BATCH];   // max of  ford(x)  (identity 0)
__device__ unsigned int g_hist[BATCH * NBINS];
__device__ float        g_entsum;
__device__ unsigned int g_count;

// monotonic float -> uint mapping (order-preserving)
__device__ __forceinline__ unsigned int ford(float f) {
    unsigned int u = __float_as_uint(f);
    return (u & 0x80000000u) ? ~u : (u | 0x80000000u);
}
__device__ __forceinline__ float funord(unsigned int u) {
    u = (u & 0x80000000u) ? (u ^ 0x80000000u) : ~u;
    return __uint_as_float(u);
}

__global__ void minmax_kernel(const float4* __restrict__ x) {
    const int b = blockIdx.y;
    const int nper4 = gridDim.x * (ELEMS_PER_BLOCK / 4);
    long base = (long)b * nper4 + (long)blockIdx.x * (ELEMS_PER_BLOCK / 4);

    float lmin = INFINITY, lmax = -INFINITY;
    #pragma unroll 8
    for (int i = 0; i < ELEMS_PER_BLOCK / 4 / TPB; i++) {
        float4 v = x[base + (long)i * TPB + threadIdx.x];
        lmin = fminf(fminf(fminf(lmin, v.x), v.y), fminf(v.z, v.w));
        lmax = fmaxf(fmaxf(fmaxf(lmax, v.x), v.y), fmaxf(v.z, v.w));
    }
    #pragma unroll
    for (int o = 16; o; o >>= 1) {
        lmin = fminf(lmin, __shfl_xor_sync(0xFFFFFFFFu, lmin, o));
        lmax = fmaxf(lmax, __shfl_xor_sync(0xFFFFFFFFu, lmax, o));
    }
    __shared__ float smin[TPB / 32], smax[TPB / 32];
    int w = threadIdx.x >> 5;
    if ((threadIdx.x & 31) == 0) { smin[w] = lmin; smax[w] = lmax; }
    __syncthreads();
    if (threadIdx.x == 0) {
        float m = smin[0], M = smax[0];
        #pragma unroll
        for (int i = 1; i < TPB / 32; i++) { m = fminf(m, smin[i]); M = fmaxf(M, smax[i]); }
        atomicMax(&g_minenc[b], ~ford(m));   // min via complement -> max, identity 0
        atomicMax(&g_maxenc[b], ford(M));
    }
}

__global__ void hist_kernel(const float4* __restrict__ x) {
    __shared__ unsigned int sh[NREP * NBINS];
    const int b = blockIdx.y;
    const int nper4 = gridDim.x * (ELEMS_PER_BLOCK / 4);

    for (int i = threadIdx.x; i < NREP * NBINS; i += TPB) sh[i] = 0u;
    __syncthreads();

    const float mn = funord(~g_minenc[b]);
    const float mx = funord(g_maxenc[b]);
    // torch.histc degenerate handling: min==max -> [min-1, max+1], rng=2
    const float rng = (mx > mn) ? (mx - mn) : 2.0f;
    const float lo  = (mx > mn) ? mn : (mn - 1.0f);
    const float scale = (float)NBINS / rng;   // matches jnp: NBINS / rng in f32

    unsigned int* myh = sh + ((threadIdx.x >> 5) & (NREP - 1)) * NBINS;
    long base = (long)b * nper4 + (long)blockIdx.x * (ELEMS_PER_BLOCK / 4);

    #pragma unroll 8
    for (int i = 0; i < ELEMS_PER_BLOCK / 4 / TPB; i++) {
        float4 v = x[base + (long)i * TPB + threadIdx.x];
        int i0 = min(max((int)((v.x - lo) * scale), 0), NBINS - 1);
        int i1 = min(max((int)((v.y - lo) * scale), 0), NBINS - 1);
        int i2 = min(max((int)((v.z - lo) * scale), 0), NBINS - 1);
        int i3 = min(max((int)((v.w - lo) * scale), 0), NBINS - 1);
        atomicAdd(&myh[i0], 1u);
        atomicAdd(&myh[i1], 1u);
        atomicAdd(&myh[i2], 1u);
        atomicAdd(&myh[i3], 1u);
    }
    __syncthreads();

    for (int bin = threadIdx.x; bin < NBINS; bin += TPB) {
        unsigned int s = 0;
        #pragma unroll
        for (int r = 0; r < NREP; r++) s += sh[r * NBINS + bin];
        if (s) atomicAdd(&g_hist[b * NBINS + bin], s);
    }
}

// H(b) = log2(N) - (1/N) * sum_h h*log2(h); last block writes mean and resets
// ALL device state to zero so the next graph replay starts clean.
__global__ void entropy_kernel(float* out, float invN, float log2N) {
    const int b = blockIdx.x;
    unsigned int h = g_hist[b * NBINS + threadIdx.x];
    g_hist[b * NBINS + threadIdx.x] = 0u;             // reset for next replay
    float term = (h > 0u) ? (float)h * log2f((float)h) : 0.0f;
    #pragma unroll
    for (int o = 16; o; o >>= 1) term += __shfl_xor_sync(0xFFFFFFFFu, term, o);
    __shared__ float s[TPB / 32];
    if ((threadIdx.x & 31) == 0) s[threadIdx.x >> 5] = term;
    __syncthreads();
    if (threadIdx.x == 0) {
        float sum = 0.0f;
        #pragma unroll
        for (int i = 0; i < TPB / 32; i++) sum += s[i];
        float ent = log2N - sum * invN;
        atomicAdd(&g_entsum, ent);
        g_minenc[b] = 0u;                             // reset min/max state
        g_maxenc[b] = 0u;
        __threadfence();
        unsigned int old = atomicAdd(&g_count, 1u);
        if (old == BATCH - 1) {
            float total = atomicAdd(&g_entsum, 0.0f); // coherent read of final sum
            out[0] = total * (1.0f / BATCH);
            g_entsum = 0.0f;                          // reset accumulators
            g_count = 0u;
        }
    }
}

extern "C" void kernel_launch(void* const* d_in, const int* in_sizes, int n_in,
                              void* d_out, int out_size) {
    const float4* x = (const float4*)d_in[0];
    float* out = (float*)d_out;

    const int n = in_sizes[0];                          // 64*3*512*512
    const int nper = n / BATCH;                         // 786432
    const int blocksPerBatch = nper / ELEMS_PER_BLOCK;  // 24

    dim3 grid(blocksPerBatch, BATCH);
    minmax_kernel<<<grid, TPB>>>(x);
    hist_kernel<<<grid, TPB>>>(x);

    float invN = 1.0f / (float)nper;
    float log2N = log2f((float)nper);
    entropy_kernel<<<BATCH, TPB>>>(out, invN, log2N);
}